// round 8
// baseline (speedup 1.0000x reference)
#include <cuda_runtime.h>
#include <cuda_bf16.h>
#include <cstdint>

#define DD    128
#define BD    16384
#define SQ36  0.28867513459481287f

// ---- dynamic smem byte offsets ----
#define RAWA  0            // fp32 A0 raw [128x128], pitch 512B, 16B-chunk XOR (row&7)
#define RAWW  65536        // fp32 W raw, same layout  (both dead after phase A)
#define TILES 131072       // bf16 A tile (32KB) + bf16 W tile (32KB); reused as fp32 comm (64KB)
#define WTILE (TILES + 32768)
#define VOFF  196608       // v[128] fp32
#define PSOFF 197120       // ps[512] fp32, layout [r*4+q]
#define SMEM_REQ 199680

__device__ __forceinline__ uint32_t smem_u32(const void* p) {
    uint32_t a;
    asm("{ .reg .u64 t; cvta.to.shared.u64 t, %1; cvt.u32.u64 %0, t; }" : "=r"(a) : "l"(p));
    return a;
}
__device__ __forceinline__ void ldsm_x4(uint32_t* r, uint32_t addr) {
    asm volatile("ldmatrix.sync.aligned.m8n8.x4.shared.b16 {%0,%1,%2,%3}, [%4];"
                 : "=r"(r[0]), "=r"(r[1]), "=r"(r[2]), "=r"(r[3]) : "r"(addr));
}
__device__ __forceinline__ void ldsm_x4t(uint32_t* r, uint32_t addr) {
    asm volatile("ldmatrix.sync.aligned.m8n8.x4.trans.shared.b16 {%0,%1,%2,%3}, [%4];"
                 : "=r"(r[0]), "=r"(r[1]), "=r"(r[2]), "=r"(r[3]) : "r"(addr));
}
__device__ __forceinline__ void mma16816(float* d, const uint32_t* a, const uint32_t* b) {
    asm volatile("mma.sync.aligned.m16n8k16.row.col.f32.bf16.bf16.f32 "
                 "{%0,%1,%2,%3}, {%4,%5,%6,%7}, {%8,%9}, {%0,%1,%2,%3};"
                 : "+f"(d[0]), "+f"(d[1]), "+f"(d[2]), "+f"(d[3])
                 : "r"(a[0]), "r"(a[1]), "r"(a[2]), "r"(a[3]), "r"(b[0]), "r"(b[1]));
}
__device__ __forceinline__ void cp16(uint32_t dst, const void* src) {
    asm volatile("cp.async.cg.shared.global [%0], [%1], 16;" :: "r"(dst), "l"(src));
}
// bf16 tile address (pitch 256B, 16B chunks XORed per 8 rows)
__device__ __forceinline__ uint32_t taddr(uint32_t base, int row, int col) {
    int chunk = (col >> 3) ^ (row & 7);
    return base + row * 256 + (chunk << 4);
}
__device__ __forceinline__ uint32_t b2u(__nv_bfloat162 v) { return *reinterpret_cast<uint32_t*>(&v); }

__global__ __launch_bounds__(512, 1)
void magnus_kernel(const float* __restrict__ t0, const float* __restrict__ hp,
                   const float* __restrict__ y0,
                   const float* __restrict__ A0, const float* __restrict__ Wm,
                   float* __restrict__ out, int B)
{
    extern __shared__ char sm[];
    const uint32_t sb = smem_u32(sm);

    const int tid  = threadIdx.x;
    const int lane = tid & 31;
    const int wid  = tid >> 5;
    const int r    = tid >> 2;     // owned Omega row
    const int q    = tid & 3;      // owned 32-col quarter

    const float h   = hp[0];
    const float hh  = 0.5f * h;
    const float c12 = h * h * h * (1.0f / 12.0f);

    float* v  = (float*)(sm + VOFF);
    float* ps = (float*)(sm + PSOFF);

    const int step = gridDim.x;
    int b = blockIdx.x;

    // ---- prime prefetch of batch b ----
    {
        const char* sA = (const char*)(A0 + (size_t)b * BD);
        const char* sW = (const char*)(Wm + (size_t)b * BD);
        #pragma unroll
        for (int it = 0; it < 8; ++it) {
            int i = tid + 512 * it;
            int row = i >> 5, ch = i & 31;
            uint32_t off = (uint32_t)(row * 512 + ((ch ^ (row & 7)) << 4));
            cp16(sb + RAWA + off, sA + (size_t)i * 16);
            cp16(sb + RAWW + off, sW + (size_t)i * 16);
        }
        asm volatile("cp.async.commit_group;" ::: "memory");
    }

    for (; b < B; b += step) {
        const float t0b = t0[b];
        const float t1  = t0b + (0.5f - SQ36) * h;
        const float t2  = t0b + (0.5f + SQ36) * h;

        asm volatile("cp.async.wait_group 0;" ::: "memory");
        __syncthreads();

        // ---- Phase A: raw smem -> A1/A2 STG + bf16 tiles (NO Omega regs here) ----
        // Thread (r,q) owns row r, chunks 8q..8q+7 — the exact addresses phase D re-reads.
        float* o1base = out + (size_t)B * DD + (size_t)b * BD;
        float* o2base = o1base + (size_t)B * BD;
        float4* o1 = (float4*)o1base;
        float4* o2 = (float4*)o2base;

        #pragma unroll
        for (int j = 0; j < 8; ++j) {
            int jj = (j + 2 * q) & 7;
            int ch = 8 * q + jj;               // 16B chunk in row (0..31)
            uint32_t roff = (uint32_t)(r * 512 + ((ch ^ (r & 7)) << 4));
            float4 a = *(const float4*)(sm + RAWA + roff);
            float4 w = *(const float4*)(sm + RAWW + roff);
            float4 x1, x2;
            x1.x = fmaf(t1, w.x, a.x); x1.y = fmaf(t1, w.y, a.y);
            x1.z = fmaf(t1, w.z, a.z); x1.w = fmaf(t1, w.w, a.w);
            x2.x = fmaf(t2, w.x, a.x); x2.y = fmaf(t2, w.y, a.y);
            x2.z = fmaf(t2, w.z, a.z); x2.w = fmaf(t2, w.w, a.w);
            int gidx = r * 32 + ch;
            o1[gidx] = x1;
            o2[gidx] = x2;
            uint32_t toff = (uint32_t)(r * 256 + (((ch >> 1) ^ (r & 7)) << 4) + ((ch & 1) << 3));
            uint2 pa, pw;
            pa.x = b2u(__floats2bfloat162_rn(a.x, a.y)); pa.y = b2u(__floats2bfloat162_rn(a.z, a.w));
            pw.x = b2u(__floats2bfloat162_rn(w.x, w.y)); pw.y = b2u(__floats2bfloat162_rn(w.z, w.w));
            *(uint2*)(sm + TILES + toff) = pa;
            *(uint2*)(sm + WTILE + toff) = pw;
        }
        __syncthreads();   // raw fully consumed; tiles complete

        // ---- Prefetch batch b+1 (overlaps MMA + epilogue + Omega-build + Taylor) ----
        if (b + step < B) {
            const char* sA = (const char*)(A0 + (size_t)(b + step) * BD);
            const char* sW = (const char*)(Wm + (size_t)(b + step) * BD);
            #pragma unroll
            for (int it = 0; it < 8; ++it) {
                int i = tid + 512 * it;
                int row = i >> 5, ch = i & 31;
                uint32_t off = (uint32_t)(row * 512 + ((ch ^ (row & 7)) << 4));
                cp16(sb + RAWA + off, sA + (size_t)i * 16);
                cp16(sb + RAWW + off, sW + (size_t)i * 16);
            }
            asm volatile("cp.async.commit_group;" ::: "memory");
        }

        // ---- Phase B: comm = A0@W + (-W)@A0; 4x4 warp grid, 32x32 tile/warp ----
        const uint32_t aA = sb + TILES;
        const uint32_t aW = sb + WTILE;
        const int m0 = (wid >> 2) << 5;
        const int n0 = (wid & 3) << 5;
        const int arow = lane & 15;
        const int acol = (lane >> 4) << 3;

        float acc[2][4][4];
        #pragma unroll
        for (int mh = 0; mh < 2; ++mh)
            #pragma unroll
            for (int nt = 0; nt < 4; ++nt)
                #pragma unroll
                for (int rr = 0; rr < 4; ++rr) acc[mh][nt][rr] = 0.0f;

        #pragma unroll
        for (int k0 = 0; k0 < DD; k0 += 16) {
            uint32_t aA1[4], aA2[4], aW1[4], aW2[4];
            ldsm_x4(aA1, taddr(aA, m0 + arow,      k0 + acol));
            ldsm_x4(aA2, taddr(aA, m0 + 16 + arow, k0 + acol));
            ldsm_x4(aW1, taddr(aW, m0 + arow,      k0 + acol));
            ldsm_x4(aW2, taddr(aW, m0 + 16 + arow, k0 + acol));
            #pragma unroll
            for (int qq = 0; qq < 4; ++qq) { aW1[qq] ^= 0x80008000u; aW2[qq] ^= 0x80008000u; }
            #pragma unroll
            for (int nn = 0; nn < 2; ++nn) {
                uint32_t bW[4], bA[4];
                ldsm_x4t(bW, taddr(aW, k0 + arow, n0 + 16 * nn + acol));
                ldsm_x4t(bA, taddr(aA, k0 + arow, n0 + 16 * nn + acol));
                mma16816(acc[0][2 * nn],     aA1, bW);
                mma16816(acc[0][2 * nn + 1], aA1, bW + 2);
                mma16816(acc[1][2 * nn],     aA2, bW);
                mma16816(acc[1][2 * nn + 1], aA2, bW + 2);
                mma16816(acc[0][2 * nn],     aW1, bA);
                mma16816(acc[0][2 * nn + 1], aW1, bA + 2);
                mma16816(acc[1][2 * nn],     aW2, bA);
                mma16816(acc[1][2 * nn + 1], aW2, bA + 2);
            }
        }
        __syncthreads();   // tile reads complete; TILES reusable as comm

        // ---- Phase C: -c12*comm -> TILES (fp32, pitch 512B, chunk XOR row&7); v init ----
        {
            const int lr = lane >> 2;
            const int lc = (lane & 3) << 1;
            #pragma unroll
            for (int mh = 0; mh < 2; ++mh)
                #pragma unroll
                for (int nt = 0; nt < 4; ++nt)
                    #pragma unroll
                    for (int half = 0; half < 2; ++half) {
                        int row = m0 + 16 * mh + lr + 8 * half;
                        int col = n0 + 8 * nt + lc;
                        uint32_t off = (uint32_t)(row * 512 + (((col >> 2) ^ (row & 7)) << 4) + ((col & 3) << 2));
                        float2 val;
                        val.x = -c12 * acc[mh][nt][2 * half];
                        val.y = -c12 * acc[mh][nt][2 * half + 1];
                        *(float2*)(sm + TILES + off) = val;
                    }
        }
        if (tid < DD) v[tid] = y0[(size_t)b * DD + tid];
        __syncthreads();

        // ---- Phase D: om = (h/2)(A1+A2) [own L2-hot rows] - c12*comm [smem] ----
        // acc[] is dead here, so om[32] reuses those registers — no spill.
        float om[32];
        #pragma unroll
        for (int j = 0; j < 8; ++j) {
            int ch = 8 * q + ((j + 2 * q) & 7);
            int gidx = r * 32 + ch;
            float4 f1 = ((const float4*)o1base)[gidx];   // written by THIS thread in phase A
            float4 f2 = ((const float4*)o2base)[gidx];
            uint32_t roff = (uint32_t)(r * 512 + ((ch ^ (r & 7)) << 4));
            float4 cm = *(const float4*)(sm + TILES + roff);
            om[4 * j + 0] = fmaf(hh, f1.x + f2.x, cm.x);
            om[4 * j + 1] = fmaf(hh, f1.y + f2.y, cm.y);
            om[4 * j + 2] = fmaf(hh, f1.z + f2.z, cm.z);
            om[4 * j + 3] = fmaf(hh, f1.w + f2.w, cm.w);
        }

        // ---- Phase E: y = expm(Omega) @ y0, 10-term Taylor ----
        float yvreg = v[r];
        #pragma unroll 1
        for (int k = 1; k <= 10; ++k) {
            float s0 = 0.f, s1 = 0.f, s2 = 0.f, s3 = 0.f;
            #pragma unroll
            for (int j = 0; j < 8; ++j) {
                int cj = (j + 2 * q) & 7;
                float4 f = *(const float4*)(sm + VOFF + q * 128 + cj * 16);
                s0 = fmaf(om[4 * j + 0], f.x, s0);
                s1 = fmaf(om[4 * j + 1], f.y, s1);
                s2 = fmaf(om[4 * j + 2], f.z, s2);
                s3 = fmaf(om[4 * j + 3], f.w, s3);
            }
            ps[r * 4 + q] = (s0 + s1) + (s2 + s3);
            __syncthreads();
            float4 p = *(const float4*)(ps + r * 4);
            float nv = ((p.x + p.y) + (p.z + p.w)) * (1.0f / (float)k);
            yvreg += nv;
            if (q == 0) v[r] = nv;
            __syncthreads();
        }
        if (q == 0) out[(size_t)b * DD + r] = yvreg;
    }
}

extern "C" void kernel_launch(void* const* d_in, const int* in_sizes, int n_in,
                              void* d_out, int out_size) {
    const float* t0 = (const float*)d_in[0];
    const float* h  = (const float*)d_in[1];
    const float* y0 = (const float*)d_in[2];
    const float* A0 = (const float*)d_in[3];
    const float* W  = (const float*)d_in[4];
    const int B = in_sizes[0];

    int grid = B < 152 ? B : 152;
    cudaFuncSetAttribute(magnus_kernel, cudaFuncAttributeMaxDynamicSharedMemorySize, SMEM_REQ);
    magnus_kernel<<<grid, 512, SMEM_REQ>>>(t0, h, y0, A0, W, (float*)d_out, B);
}

// round 10
// speedup vs baseline: 1.7157x; 1.7157x over previous
#include <cuda_runtime.h>
#include <cuda_bf16.h>
#include <cstdint>

#define DD    128
#define BD    16384
#define SQ36  0.28867513459481287f

// ---- dynamic smem byte offsets (per CTA ~97.5KB -> 2 CTAs/SM) ----
#define SHI   0        // bf16 hi(S), S=A1+A2, [128x128] pitch 256B, chunk-XOR swizzle (32KB)
#define SLO   32768    // bf16 lo(S) = bf16(S - float(hi))  (32KB)
#define WCM   65536    // bf16 W tile; overwritten with bf16(comm) after MMA (32KB)
#define VOFF  98304    // v[128] fp32
#define PSOFF 98816    // ps[256] fp32, layout [2r+half]
#define SMEM_REQ 99840

__device__ __forceinline__ uint32_t smem_u32(const void* p) {
    uint32_t a;
    asm("{ .reg .u64 t; cvta.to.shared.u64 t, %1; cvt.u32.u64 %0, t; }" : "=r"(a) : "l"(p));
    return a;
}
__device__ __forceinline__ void ldsm_x4(uint32_t* r, uint32_t addr) {
    asm volatile("ldmatrix.sync.aligned.m8n8.x4.shared.b16 {%0,%1,%2,%3}, [%4];"
                 : "=r"(r[0]), "=r"(r[1]), "=r"(r[2]), "=r"(r[3]) : "r"(addr));
}
__device__ __forceinline__ void ldsm_x4t(uint32_t* r, uint32_t addr) {
    asm volatile("ldmatrix.sync.aligned.m8n8.x4.trans.shared.b16 {%0,%1,%2,%3}, [%4];"
                 : "=r"(r[0]), "=r"(r[1]), "=r"(r[2]), "=r"(r[3]) : "r"(addr));
}
__device__ __forceinline__ void mma16816(float* d, const uint32_t* a, const uint32_t* b) {
    asm volatile("mma.sync.aligned.m16n8k16.row.col.f32.bf16.bf16.f32 "
                 "{%0,%1,%2,%3}, {%4,%5,%6,%7}, {%8,%9}, {%0,%1,%2,%3};"
                 : "+f"(d[0]), "+f"(d[1]), "+f"(d[2]), "+f"(d[3])
                 : "r"(a[0]), "r"(a[1]), "r"(a[2]), "r"(a[3]), "r"(b[0]), "r"(b[1]));
}
// bf16 tile address: pitch 256B/row (16 chunks of 16B), chunk ^= row&7 (low 3 bits)
__device__ __forceinline__ uint32_t taddr(uint32_t base, int row, int col) {
    int chunk = (col >> 3) ^ (row & 7);
    return base + row * 256 + (chunk << 4);
}
__device__ __forceinline__ uint32_t b2u(__nv_bfloat162 v) { return *reinterpret_cast<uint32_t*>(&v); }

__global__ __launch_bounds__(256, 2)
void magnus_kernel(const float* __restrict__ t0, const float* __restrict__ hp,
                   const float* __restrict__ y0,
                   const float* __restrict__ A0, const float* __restrict__ Wm,
                   float* __restrict__ out, int B)
{
    extern __shared__ char sm[];
    const uint32_t sb = smem_u32(sm);

    const int b    = blockIdx.x;
    const int tid  = threadIdx.x;
    const int lane = tid & 31;
    const int wid  = tid >> 5;

    const float h   = hp[0];
    const float t0b = t0[b];
    const float t1  = t0b + (0.5f - SQ36) * h;
    const float t2  = t0b + (0.5f + SQ36) * h;
    const float h2  = 0.5f * h;
    const float c24 = h * h * h * (1.0f / 24.0f);

    float* v  = (float*)(sm + VOFF);
    float* ps = (float*)(sm + PSOFF);

    // ---- Phase 1: LDG A0,W -> A1/A2 STG + S hi/lo bf16 tiles + W bf16 tile ----
    const float4* A0g = (const float4*)(A0 + (size_t)b * BD);
    const float4* Wg  = (const float4*)(Wm + (size_t)b * BD);
    float4* o1 = (float4*)(out + (size_t)B * DD + (size_t)b * BD);
    float4* o2 = (float4*)(out + (size_t)B * DD + (size_t)B * BD + (size_t)b * BD);

    #pragma unroll
    for (int it = 0; it < 16; ++it) {
        int i   = tid + 256 * it;
        int row = i >> 5;
        int ch  = i & 31;            // 16B fp32 chunk in row
        float4 a = A0g[i];
        float4 w = Wg[i];
        float4 x1, x2, S;
        x1.x = fmaf(t1, w.x, a.x); x1.y = fmaf(t1, w.y, a.y);
        x1.z = fmaf(t1, w.z, a.z); x1.w = fmaf(t1, w.w, a.w);
        x2.x = fmaf(t2, w.x, a.x); x2.y = fmaf(t2, w.y, a.y);
        x2.z = fmaf(t2, w.z, a.z); x2.w = fmaf(t2, w.w, a.w);
        o1[i] = x1;
        o2[i] = x2;
        S.x = x1.x + x2.x; S.y = x1.y + x2.y;
        S.z = x1.z + x2.z; S.w = x1.w + x2.w;
        // hi/lo split of S
        __nv_bfloat16 hx = __float2bfloat16(S.x), hy = __float2bfloat16(S.y);
        __nv_bfloat16 hz = __float2bfloat16(S.z), hw = __float2bfloat16(S.w);
        float lx = S.x - __bfloat162float(hx), ly = S.y - __bfloat162float(hy);
        float lz = S.z - __bfloat162float(hz), lw = S.w - __bfloat162float(hw);
        uint2 phi, plo, pw;
        phi.x = b2u(__halves2bfloat162(hx, hy));
        phi.y = b2u(__halves2bfloat162(hz, hw));
        plo.x = b2u(__floats2bfloat162_rn(lx, ly));
        plo.y = b2u(__floats2bfloat162_rn(lz, lw));
        pw.x  = b2u(__floats2bfloat162_rn(w.x, w.y));
        pw.y  = b2u(__floats2bfloat162_rn(w.z, w.w));
        uint32_t toff = (uint32_t)(row * 256 + (((ch >> 1) ^ (row & 7)) << 4) + ((ch & 1) << 3));
        *(uint2*)(sm + SHI + toff) = phi;
        *(uint2*)(sm + SLO + toff) = plo;
        *(uint2*)(sm + WCM + toff) = pw;
    }
    __syncthreads();

    // ---- Phase 2: CM = S@W + (-W)@S  (= [S,W]); 2x4 warp grid, 64x32/warp ----
    const uint32_t aS = sb + SHI;
    const uint32_t aW = sb + WCM;
    const int m0 = (wid >> 2) << 6;   // 0 or 64
    const int n0 = (wid & 3) << 5;    // 0,32,64,96
    const int arow = lane & 15;
    const int acol = (lane >> 4) << 3;

    float acc[4][4][4];
    #pragma unroll
    for (int mh = 0; mh < 4; ++mh)
        #pragma unroll
        for (int nt = 0; nt < 4; ++nt)
            #pragma unroll
            for (int rr = 0; rr < 4; ++rr) acc[mh][nt][rr] = 0.0f;

    #pragma unroll
    for (int k0 = 0; k0 < DD; k0 += 16) {
        uint32_t fs[4][4], fw[4][4];
        #pragma unroll
        for (int mh = 0; mh < 4; ++mh) {
            ldsm_x4(fs[mh], taddr(aS, m0 + 16 * mh + arow, k0 + acol));
            ldsm_x4(fw[mh], taddr(aW, m0 + 16 * mh + arow, k0 + acol));
            #pragma unroll
            for (int qq = 0; qq < 4; ++qq) fw[mh][qq] ^= 0x80008000u;   // -W
        }
        #pragma unroll
        for (int nn = 0; nn < 2; ++nn) {
            uint32_t bW[4], bS[4];
            ldsm_x4t(bW, taddr(aW, k0 + arow, n0 + 16 * nn + acol));
            ldsm_x4t(bS, taddr(aS, k0 + arow, n0 + 16 * nn + acol));
            #pragma unroll
            for (int mh = 0; mh < 4; ++mh) {
                mma16816(acc[mh][2 * nn],     fs[mh], bW);
                mma16816(acc[mh][2 * nn + 1], fs[mh], bW + 2);
                mma16816(acc[mh][2 * nn],     fw[mh], bS);
                mma16816(acc[mh][2 * nn + 1], fw[mh], bS + 2);
            }
        }
    }
    __syncthreads();   // all ldsm of W tile done -> WCM reusable

    // ---- Phase 3: bf16(CM) -> WCM region; v <- y0 ----
    {
        const int lr = lane >> 2;
        const int lc = (lane & 3) << 1;
        #pragma unroll
        for (int mh = 0; mh < 4; ++mh)
            #pragma unroll
            for (int nt = 0; nt < 4; ++nt)
                #pragma unroll
                for (int half = 0; half < 2; ++half) {
                    int row = m0 + 16 * mh + lr + 8 * half;
                    int col = n0 + 8 * nt + lc;
                    uint32_t addr = (uint32_t)(row * 256 + (((col >> 3) ^ (row & 7)) << 4) + ((col & 7) << 1));
                    *(uint32_t*)(sm + WCM + addr) =
                        b2u(__floats2bfloat162_rn(acc[mh][nt][2 * half], acc[mh][nt][2 * half + 1]));
                }
    }
    if (tid < DD) v[tid] = y0[(size_t)b * DD + tid];
    __syncthreads();

    // ---- Phase 4: build om[64] = (h/2)(hi+lo) - c24*CM for row r, half ----
    const int r    = tid >> 1;
    const int half = tid & 1;

    float om[64];
    #pragma unroll
    for (int j = 0; j < 8; ++j) {
        // logical chunk j of this half lives at physical chunk 8*half + (j ^ (r&7))
        uint32_t cc = (uint32_t)(r * 256 + ((8 * half + (j ^ (r & 7))) << 4));
        uint4 uh = *(const uint4*)(sm + SHI + cc);
        uint4 ul = *(const uint4*)(sm + SLO + cc);
        uint4 uc = *(const uint4*)(sm + WCM + cc);
        int jb = j * 8;                  // FIXED: logical index (was double-XORed)
        const uint32_t hs[4] = {uh.x, uh.y, uh.z, uh.w};
        const uint32_t ls[4] = {ul.x, ul.y, ul.z, ul.w};
        const uint32_t cs[4] = {uc.x, uc.y, uc.z, uc.w};
        #pragma unroll
        for (int t = 0; t < 4; ++t) {
            float2 fh = __bfloat1622float2(*(const __nv_bfloat162*)&hs[t]);
            float2 fl = __bfloat1622float2(*(const __nv_bfloat162*)&ls[t]);
            float2 fc = __bfloat1622float2(*(const __nv_bfloat162*)&cs[t]);
            om[jb + 2 * t + 0] = fmaf(h2, fh.x + fl.x, -c24 * fc.x);
            om[jb + 2 * t + 1] = fmaf(h2, fh.y + fl.y, -c24 * fc.y);
        }
    }

    // ---- Phase 5: y = expm(Omega) @ y0, 10-term Taylor ----
    // om[c] corresponds to column 64*half + c.
    float yvreg = v[r];
    const float4* vv = (const float4*)(v + 64 * half);
    #pragma unroll 1
    for (int k = 1; k <= 10; ++k) {
        float s0 = 0.f, s1 = 0.f, s2 = 0.f, s3 = 0.f;
        #pragma unroll
        for (int f4 = 0; f4 < 16; ++f4) {
            float4 f = vv[f4];
            s0 = fmaf(om[4 * f4 + 0], f.x, s0);
            s1 = fmaf(om[4 * f4 + 1], f.y, s1);
            s2 = fmaf(om[4 * f4 + 2], f.z, s2);
            s3 = fmaf(om[4 * f4 + 3], f.w, s3);
        }
        ps[2 * r + half] = (s0 + s1) + (s2 + s3);
        __syncthreads();
        float2 p = *(const float2*)(ps + 2 * r);
        float nv = (p.x + p.y) * (1.0f / (float)k);
        yvreg += nv;
        if (half == 0) v[r] = nv;
        __syncthreads();
    }
    if (half == 0) out[(size_t)b * DD + r] = yvreg;
}

extern "C" void kernel_launch(void* const* d_in, const int* in_sizes, int n_in,
                              void* d_out, int out_size) {
    const float* t0 = (const float*)d_in[0];
    const float* h  = (const float*)d_in[1];
    const float* y0 = (const float*)d_in[2];
    const float* A0 = (const float*)d_in[3];
    const float* W  = (const float*)d_in[4];
    const int B = in_sizes[0];

    cudaFuncSetAttribute(magnus_kernel, cudaFuncAttributeMaxDynamicSharedMemorySize, SMEM_REQ);
    magnus_kernel<<<B, 256, SMEM_REQ>>>(t0, h, y0, A0, W, (float*)d_out, B);
}

// round 11
// speedup vs baseline: 1.7585x; 1.0249x over previous
#include <cuda_runtime.h>
#include <cuda_fp16.h>
#include <cstdint>

#define DD    128
#define BD    16384
#define SQ36  0.28867513459481287f

// ---- dynamic smem byte offsets (per CTA ~65.5KB -> 3 CTAs/SM) ----
#define SHI   0        // fp16 S = A1+A2, [128x128] pitch 256B, chunk-XOR swizzle (32KB)
#define WCM   32768    // fp16 W tile; overwritten with fp16 comm after MMA (32KB)
#define VOFF  65536    // v[128] fp32
#define PSOFF 66048    // ps[256] fp32, layout [2r+half]
#define SMEM_REQ 67072

__device__ __forceinline__ uint32_t smem_u32(const void* p) {
    uint32_t a;
    asm("{ .reg .u64 t; cvta.to.shared.u64 t, %1; cvt.u32.u64 %0, t; }" : "=r"(a) : "l"(p));
    return a;
}
__device__ __forceinline__ void ldsm_x4(uint32_t* r, uint32_t addr) {
    asm volatile("ldmatrix.sync.aligned.m8n8.x4.shared.b16 {%0,%1,%2,%3}, [%4];"
                 : "=r"(r[0]), "=r"(r[1]), "=r"(r[2]), "=r"(r[3]) : "r"(addr));
}
__device__ __forceinline__ void ldsm_x4t(uint32_t* r, uint32_t addr) {
    asm volatile("ldmatrix.sync.aligned.m8n8.x4.trans.shared.b16 {%0,%1,%2,%3}, [%4];"
                 : "=r"(r[0]), "=r"(r[1]), "=r"(r[2]), "=r"(r[3]) : "r"(addr));
}
// fp16 in, fp16 accum (d packed f16x2: d0 = row lr, d1 = row lr+8)
__device__ __forceinline__ void mma16816h(uint32_t* d, const uint32_t* a, const uint32_t* b) {
    asm volatile("mma.sync.aligned.m16n8k16.row.col.f16.f16.f16.f16 "
                 "{%0,%1}, {%2,%3,%4,%5}, {%6,%7}, {%0,%1};"
                 : "+r"(d[0]), "+r"(d[1])
                 : "r"(a[0]), "r"(a[1]), "r"(a[2]), "r"(a[3]), "r"(b[0]), "r"(b[1]));
}
// fp16 tile address: pitch 256B/row (16 chunks of 16B = 8 cols each), chunk ^= row&7
__device__ __forceinline__ uint32_t taddr(uint32_t base, int row, int col) {
    int chunk = (col >> 3) ^ (row & 7);
    return base + row * 256 + (chunk << 4);
}
__device__ __forceinline__ uint32_t h2u(__half2 v) { return *reinterpret_cast<uint32_t*>(&v); }

__global__ __launch_bounds__(256, 3)
void magnus_kernel(const float* __restrict__ t0, const float* __restrict__ hp,
                   const float* __restrict__ y0,
                   const float* __restrict__ A0, const float* __restrict__ Wm,
                   float* __restrict__ out, int B)
{
    extern __shared__ char sm[];
    const uint32_t sb = smem_u32(sm);

    const int b    = blockIdx.x;
    const int tid  = threadIdx.x;
    const int lane = tid & 31;
    const int wid  = tid >> 5;

    const float h   = hp[0];
    const float t0b = t0[b];
    const float t1  = t0b + (0.5f - SQ36) * h;
    const float t2  = t0b + (0.5f + SQ36) * h;
    const float h2  = 0.5f * h;
    const float c24 = h * h * h * (1.0f / 24.0f);

    float* v  = (float*)(sm + VOFF);
    float* ps = (float*)(sm + PSOFF);

    // ---- Phase 1: LDG A0,W -> A1/A2 STG + fp16 S tile + fp16 W tile ----
    const float4* A0g = (const float4*)(A0 + (size_t)b * BD);
    const float4* Wg  = (const float4*)(Wm + (size_t)b * BD);
    float4* o1 = (float4*)(out + (size_t)B * DD + (size_t)b * BD);
    float4* o2 = (float4*)(out + (size_t)B * DD + (size_t)B * BD + (size_t)b * BD);

    #pragma unroll
    for (int it = 0; it < 16; ++it) {
        int i   = tid + 256 * it;
        int row = i >> 5;
        int ch  = i & 31;            // 16B fp32 chunk (4 cols)
        float4 a = A0g[i];
        float4 w = Wg[i];
        float4 x1, x2;
        x1.x = fmaf(t1, w.x, a.x); x1.y = fmaf(t1, w.y, a.y);
        x1.z = fmaf(t1, w.z, a.z); x1.w = fmaf(t1, w.w, a.w);
        x2.x = fmaf(t2, w.x, a.x); x2.y = fmaf(t2, w.y, a.y);
        x2.z = fmaf(t2, w.z, a.z); x2.w = fmaf(t2, w.w, a.w);
        o1[i] = x1;
        o2[i] = x2;
        uint2 pS, pW;
        pS.x = h2u(__floats2half2_rn(x1.x + x2.x, x1.y + x2.y));
        pS.y = h2u(__floats2half2_rn(x1.z + x2.z, x1.w + x2.w));
        pW.x = h2u(__floats2half2_rn(w.x, w.y));
        pW.y = h2u(__floats2half2_rn(w.z, w.w));
        // fp16 tile: 4 fp32 cols -> 8 bytes; chunk index ch>>1, sub-half (ch&1)*8
        uint32_t toff = (uint32_t)(row * 256 + (((ch >> 1) ^ (row & 7)) << 4) + ((ch & 1) << 3));
        *(uint2*)(sm + SHI + toff) = pS;
        *(uint2*)(sm + WCM + toff) = pW;
    }
    __syncthreads();

    // ---- Phase 2: CM = S@W + (-W)@S (= [S,W]); 2x4 warp grid, 64x32/warp, f16 accum ----
    const uint32_t aS = sb + SHI;
    const uint32_t aW = sb + WCM;
    const int m0 = (wid >> 2) << 6;   // 0 or 64
    const int n0 = (wid & 3) << 5;    // 0,32,64,96
    const int arow = lane & 15;
    const int acol = (lane >> 4) << 3;

    uint32_t acc[4][4][2];            // [mh][nt][row-half], packed f16x2 (col pair)
    #pragma unroll
    for (int mh = 0; mh < 4; ++mh)
        #pragma unroll
        for (int nt = 0; nt < 4; ++nt) { acc[mh][nt][0] = 0u; acc[mh][nt][1] = 0u; }

    #pragma unroll
    for (int k0 = 0; k0 < DD; k0 += 16) {
        uint32_t fs[4][4], fw[4][4];
        #pragma unroll
        for (int mh = 0; mh < 4; ++mh) {
            ldsm_x4(fs[mh], taddr(aS, m0 + 16 * mh + arow, k0 + acol));
            ldsm_x4(fw[mh], taddr(aW, m0 + 16 * mh + arow, k0 + acol));
            #pragma unroll
            for (int qq = 0; qq < 4; ++qq) fw[mh][qq] ^= 0x80008000u;   // -W
        }
        #pragma unroll
        for (int nn = 0; nn < 2; ++nn) {
            uint32_t bW[4], bS[4];
            ldsm_x4t(bW, taddr(aW, k0 + arow, n0 + 16 * nn + acol));
            ldsm_x4t(bS, taddr(aS, k0 + arow, n0 + 16 * nn + acol));
            #pragma unroll
            for (int mh = 0; mh < 4; ++mh) {
                mma16816h(acc[mh][2 * nn],     fs[mh], bW);
                mma16816h(acc[mh][2 * nn + 1], fs[mh], bW + 2);
                mma16816h(acc[mh][2 * nn],     fw[mh], bS);
                mma16816h(acc[mh][2 * nn + 1], fw[mh], bS + 2);
            }
        }
    }
    __syncthreads();   // all ldsm of W tile done -> WCM reusable

    // ---- Phase 3: fp16 CM -> WCM region (acc already packed f16x2); v <- y0 ----
    {
        const int lr = lane >> 2;
        const int lc = (lane & 3) << 1;
        #pragma unroll
        for (int mh = 0; mh < 4; ++mh)
            #pragma unroll
            for (int nt = 0; nt < 4; ++nt)
                #pragma unroll
                for (int half = 0; half < 2; ++half) {
                    int row = m0 + 16 * mh + lr + 8 * half;
                    int col = n0 + 8 * nt + lc;
                    uint32_t addr = (uint32_t)(row * 256 + (((col >> 3) ^ (row & 7)) << 4) + ((col & 7) << 1));
                    *(uint32_t*)(sm + WCM + addr) = acc[mh][nt][half];
                }
    }
    if (tid < DD) v[tid] = y0[(size_t)b * DD + tid];
    __syncthreads();

    // ---- Phase 4: om[64] = h/2 * S - c24 * CM  (row r, half) ----
    const int r    = tid >> 1;
    const int half = tid & 1;

    float om[64];
    #pragma unroll
    for (int j = 0; j < 8; ++j) {
        // logical chunk j (8 cols) of this half -> physical chunk 8*half + (j ^ (r&7))
        uint32_t cc = (uint32_t)(r * 256 + ((8 * half + (j ^ (r & 7))) << 4));
        uint4 us = *(const uint4*)(sm + SHI + cc);
        uint4 uc = *(const uint4*)(sm + WCM + cc);
        const uint32_t ss[4] = {us.x, us.y, us.z, us.w};
        const uint32_t cs[4] = {uc.x, uc.y, uc.z, uc.w};
        int jb = j * 8;
        #pragma unroll
        for (int t = 0; t < 4; ++t) {
            float2 fs = __half22float2(*(const __half2*)&ss[t]);
            float2 fc = __half22float2(*(const __half2*)&cs[t]);
            om[jb + 2 * t + 0] = fmaf(h2, fs.x, -c24 * fc.x);
            om[jb + 2 * t + 1] = fmaf(h2, fs.y, -c24 * fc.y);
        }
    }

    // ---- Phase 5: y = expm(Omega) @ y0, 7-term Taylor ----
    float yvreg = v[r];
    const float4* vv = (const float4*)(v + 64 * half);
    #pragma unroll 1
    for (int k = 1; k <= 7; ++k) {
        float s0 = 0.f, s1 = 0.f, s2 = 0.f, s3 = 0.f;
        #pragma unroll
        for (int f4 = 0; f4 < 16; ++f4) {
            float4 f = vv[f4];
            s0 = fmaf(om[4 * f4 + 0], f.x, s0);
            s1 = fmaf(om[4 * f4 + 1], f.y, s1);
            s2 = fmaf(om[4 * f4 + 2], f.z, s2);
            s3 = fmaf(om[4 * f4 + 3], f.w, s3);
        }
        ps[2 * r + half] = (s0 + s1) + (s2 + s3);
        __syncthreads();
        float2 p = *(const float2*)(ps + 2 * r);
        float nv = (p.x + p.y) * (1.0f / (float)k);
        yvreg += nv;
        if (half == 0) v[r] = nv;
        __syncthreads();
    }
    if (half == 0) out[(size_t)b * DD + r] = yvreg;
}

extern "C" void kernel_launch(void* const* d_in, const int* in_sizes, int n_in,
                              void* d_out, int out_size) {
    const float* t0 = (const float*)d_in[0];
    const float* h  = (const float*)d_in[1];
    const float* y0 = (const float*)d_in[2];
    const float* A0 = (const float*)d_in[3];
    const float* W  = (const float*)d_in[4];
    const int B = in_sizes[0];

    cudaFuncSetAttribute(magnus_kernel, cudaFuncAttributeMaxDynamicSharedMemorySize, SMEM_REQ);
    magnus_kernel<<<B, 256, SMEM_REQ>>>(t0, h, y0, A0, W, (float*)d_out, B);
}

// round 12
// speedup vs baseline: 1.8555x; 1.0552x over previous
#include <cuda_runtime.h>
#include <cuda_fp16.h>
#include <cstdint>

#define DD    128
#define BD    16384
#define SQ36  0.28867513459481287f

// ---- dynamic smem byte offsets (per CTA ~65.5KB -> 3 CTAs/SM) ----
#define SHI   0        // fp16 S = A1+A2, [128x128] pitch 256B, chunk-XOR swizzle (32KB)
#define WCM   32768    // fp16 W tile; overwritten with fp16 comm after MMA (32KB)
#define VOFF  65536    // v[128] fp32
#define PSOFF 66048    // ps[256] fp32, layout [2r+half]
#define SMEM_REQ 67072

__device__ __forceinline__ uint32_t smem_u32(const void* p) {
    uint32_t a;
    asm("{ .reg .u64 t; cvta.to.shared.u64 t, %1; cvt.u32.u64 %0, t; }" : "=r"(a) : "l"(p));
    return a;
}
__device__ __forceinline__ void ldsm_x4(uint32_t* r, uint32_t addr) {
    asm volatile("ldmatrix.sync.aligned.m8n8.x4.shared.b16 {%0,%1,%2,%3}, [%4];"
                 : "=r"(r[0]), "=r"(r[1]), "=r"(r[2]), "=r"(r[3]) : "r"(addr));
}
__device__ __forceinline__ void ldsm_x4t(uint32_t* r, uint32_t addr) {
    asm volatile("ldmatrix.sync.aligned.m8n8.x4.trans.shared.b16 {%0,%1,%2,%3}, [%4];"
                 : "=r"(r[0]), "=r"(r[1]), "=r"(r[2]), "=r"(r[3]) : "r"(addr));
}
// fp16 in, fp16 accum (d packed f16x2: d[0] = row lr, d[1] = row lr+8)
__device__ __forceinline__ void mma16816h(uint32_t* d, const uint32_t* a, const uint32_t* b) {
    asm volatile("mma.sync.aligned.m16n8k16.row.col.f16.f16.f16.f16 "
                 "{%0,%1}, {%2,%3,%4,%5}, {%6,%7}, {%0,%1};"
                 : "+r"(d[0]), "+r"(d[1])
                 : "r"(a[0]), "r"(a[1]), "r"(a[2]), "r"(a[3]), "r"(b[0]), "r"(b[1]));
}
// fp16 tile address: pitch 256B/row (16 chunks of 16B = 8 cols each), chunk ^= row&7
__device__ __forceinline__ uint32_t taddr(uint32_t base, int row, int col) {
    int chunk = (col >> 3) ^ (row & 7);
    return base + row * 256 + (chunk << 4);
}
__device__ __forceinline__ uint32_t h2u(__half2 v) { return *reinterpret_cast<uint32_t*>(&v); }

__global__ __launch_bounds__(256, 3)
void magnus_kernel(const float* __restrict__ t0, const float* __restrict__ hp,
                   const float* __restrict__ y0,
                   const float* __restrict__ A0, const float* __restrict__ Wm,
                   float* __restrict__ out, int B)
{
    extern __shared__ char sm[];
    const uint32_t sb = smem_u32(sm);

    const int b    = blockIdx.x;
    const int tid  = threadIdx.x;
    const int lane = tid & 31;
    const int wid  = tid >> 5;

    const float h   = hp[0];
    const float t0b = t0[b];
    const float t1  = t0b + (0.5f - SQ36) * h;
    const float t2  = t0b + (0.5f + SQ36) * h;
    const float h2  = 0.5f * h;
    const float c24 = h * h * h * (1.0f / 24.0f);

    float* v  = (float*)(sm + VOFF);
    float* ps = (float*)(sm + PSOFF);

    // ---- Phase 1: LDG A0,W (double-buffered, MLP~8) -> A1/A2 STG + fp16 tiles ----
    const float4* A0g = (const float4*)(A0 + (size_t)b * BD);
    const float4* Wg  = (const float4*)(Wm + (size_t)b * BD);
    float4* o1 = (float4*)(out + (size_t)B * DD + (size_t)b * BD);
    float4* o2 = (float4*)(out + (size_t)B * DD + (size_t)B * BD + (size_t)b * BD);

    // y0 -> v early: its latency hides behind the tile build
    float y0v = (tid < DD) ? y0[(size_t)b * DD + tid] : 0.0f;

    {
        float4 pa[2][2], pw[2][2];
        #pragma unroll
        for (int u = 0; u < 2; ++u) {
            int i = tid + 256 * u;
            pa[0][u] = A0g[i];
            pw[0][u] = Wg[i];
        }
        #pragma unroll
        for (int gp = 0; gp < 8; ++gp) {
            int cur = gp & 1;
            if (gp < 7) {
                #pragma unroll
                for (int u = 0; u < 2; ++u) {
                    int i = tid + 256 * (2 * (gp + 1) + u);
                    pa[cur ^ 1][u] = A0g[i];
                    pw[cur ^ 1][u] = Wg[i];
                }
            }
            #pragma unroll
            for (int u = 0; u < 2; ++u) {
                int i   = tid + 256 * (2 * gp + u);
                int row = i >> 5;
                int ch  = i & 31;            // 16B fp32 chunk (4 cols)
                float4 a = pa[cur][u];
                float4 w = pw[cur][u];
                float4 x1, x2;
                x1.x = fmaf(t1, w.x, a.x); x1.y = fmaf(t1, w.y, a.y);
                x1.z = fmaf(t1, w.z, a.z); x1.w = fmaf(t1, w.w, a.w);
                x2.x = fmaf(t2, w.x, a.x); x2.y = fmaf(t2, w.y, a.y);
                x2.z = fmaf(t2, w.z, a.z); x2.w = fmaf(t2, w.w, a.w);
                o1[i] = x1;
                o2[i] = x2;
                uint2 pS, pW;
                pS.x = h2u(__floats2half2_rn(x1.x + x2.x, x1.y + x2.y));
                pS.y = h2u(__floats2half2_rn(x1.z + x2.z, x1.w + x2.w));
                pW.x = h2u(__floats2half2_rn(w.x, w.y));
                pW.y = h2u(__floats2half2_rn(w.z, w.w));
                uint32_t toff = (uint32_t)(row * 256 + (((ch >> 1) ^ (row & 7)) << 4) + ((ch & 1) << 3));
                *(uint2*)(sm + SHI + toff) = pS;
                *(uint2*)(sm + WCM + toff) = pW;
            }
        }
    }
    if (tid < DD) v[tid] = y0v;
    __syncthreads();

    // ---- Phase 2: CM = S@W + (-W)@S (= [S,W]); 2x4 warp grid, 64x32/warp, f16 accum ----
    const uint32_t aS = sb + SHI;
    const uint32_t aW = sb + WCM;
    const int m0 = (wid >> 2) << 6;   // 0 or 64
    const int n0 = (wid & 3) << 5;    // 0,32,64,96
    const int arow = lane & 15;
    const int acol = (lane >> 4) << 3;

    uint32_t acc[4][4][2];            // [mh][nt][row-half], packed f16x2
    #pragma unroll
    for (int mh = 0; mh < 4; ++mh)
        #pragma unroll
        for (int nt = 0; nt < 4; ++nt) { acc[mh][nt][0] = 0u; acc[mh][nt][1] = 0u; }

    #pragma unroll
    for (int k0 = 0; k0 < DD; k0 += 16) {
        uint32_t fs[4][4], fw[4][4];
        #pragma unroll
        for (int mh = 0; mh < 4; ++mh) {
            ldsm_x4(fs[mh], taddr(aS, m0 + 16 * mh + arow, k0 + acol));
            ldsm_x4(fw[mh], taddr(aW, m0 + 16 * mh + arow, k0 + acol));
            #pragma unroll
            for (int qq = 0; qq < 4; ++qq) fw[mh][qq] ^= 0x80008000u;   // -W
        }
        #pragma unroll
        for (int nn = 0; nn < 2; ++nn) {
            uint32_t bW[4], bS[4];
            ldsm_x4t(bW, taddr(aW, k0 + arow, n0 + 16 * nn + acol));
            ldsm_x4t(bS, taddr(aS, k0 + arow, n0 + 16 * nn + acol));
            #pragma unroll
            for (int mh = 0; mh < 4; ++mh) {
                mma16816h(acc[mh][2 * nn],     fs[mh], bW);
                mma16816h(acc[mh][2 * nn + 1], fs[mh], bW + 2);
                mma16816h(acc[mh][2 * nn],     fw[mh], bS);
                mma16816h(acc[mh][2 * nn + 1], fw[mh], bS + 2);
            }
        }
    }
    __syncthreads();   // all ldsm of W tile done -> WCM reusable

    // ---- Phase 3: fp16 CM -> WCM region (acc already packed f16x2) ----
    {
        const int lr = lane >> 2;
        const int lc = (lane & 3) << 1;
        #pragma unroll
        for (int mh = 0; mh < 4; ++mh)
            #pragma unroll
            for (int nt = 0; nt < 4; ++nt)
                #pragma unroll
                for (int half = 0; half < 2; ++half) {
                    int row = m0 + 16 * mh + lr + 8 * half;
                    int col = n0 + 8 * nt + lc;
                    uint32_t addr = (uint32_t)(row * 256 + (((col >> 3) ^ (row & 7)) << 4) + ((col & 7) << 1));
                    *(uint32_t*)(sm + WCM + addr) = acc[mh][nt][half];
                }
    }
    __syncthreads();

    // ---- Phase 4: om[64] = h/2 * S - c24 * CM  (row r, half) ----
    const int r    = tid >> 1;
    const int half = tid & 1;

    float om[64];
    #pragma unroll
    for (int j = 0; j < 8; ++j) {
        // logical chunk j (8 cols) of this half -> physical chunk 8*half + (j ^ (r&7))
        uint32_t cc = (uint32_t)(r * 256 + ((8 * half + (j ^ (r & 7))) << 4));
        uint4 us = *(const uint4*)(sm + SHI + cc);
        uint4 uc = *(const uint4*)(sm + WCM + cc);
        const uint32_t ss[4] = {us.x, us.y, us.z, us.w};
        const uint32_t cs[4] = {uc.x, uc.y, uc.z, uc.w};
        int jb = j * 8;
        #pragma unroll
        for (int t = 0; t < 4; ++t) {
            float2 fs = __half22float2(*(const __half2*)&ss[t]);
            float2 fc = __half22float2(*(const __half2*)&cs[t]);
            om[jb + 2 * t + 0] = fmaf(h2, fs.x, -c24 * fc.x);
            om[jb + 2 * t + 1] = fmaf(h2, fs.y, -c24 * fc.y);
        }
    }

    // ---- Phase 5: y = expm(Omega) @ y0, 7-term Taylor ----
    float yvreg = v[r];
    const float4* vv = (const float4*)(v + 64 * half);
    #pragma unroll 1
    for (int k = 1; k <= 7; ++k) {
        float s0 = 0.f, s1 = 0.f, s2 = 0.f, s3 = 0.f;
        #pragma unroll
        for (int f4 = 0; f4 < 16; ++f4) {
            float4 f = vv[f4];
            s0 = fmaf(om[4 * f4 + 0], f.x, s0);
            s1 = fmaf(om[4 * f4 + 1], f.y, s1);
            s2 = fmaf(om[4 * f4 + 2], f.z, s2);
            s3 = fmaf(om[4 * f4 + 3], f.w, s3);
        }
        ps[2 * r + half] = (s0 + s1) + (s2 + s3);
        __syncthreads();
        float2 p = *(const float2*)(ps + 2 * r);
        float nv = (p.x + p.y) * (1.0f / (float)k);
        yvreg += nv;
        if (half == 0) v[r] = nv;
        __syncthreads();
    }
    if (half == 0) out[(size_t)b * DD + r] = yvreg;
}

extern "C" void kernel_launch(void* const* d_in, const int* in_sizes, int n_in,
                              void* d_out, int out_size) {
    const float* t0 = (const float*)d_in[0];
    const float* h  = (const float*)d_in[1];
    const float* y0 = (const float*)d_in[2];
    const float* A0 = (const float*)d_in[3];
    const float* W  = (const float*)d_in[4];
    const int B = in_sizes[0];

    cudaFuncSetAttribute(magnus_kernel, cudaFuncAttributeMaxDynamicSharedMemorySize, SMEM_REQ);
    magnus_kernel<<<B, 256, SMEM_REQ>>>(t0, h, y0, A0, W, (float*)d_out, B);
}

// round 13
// speedup vs baseline: 2.2238x; 1.1984x over previous
#include <cuda_runtime.h>
#include <cuda_fp16.h>
#include <cstdint>

#define DD    128
#define BD    16384
#define SQ36  0.28867513459481287f

// ---- smem: two ping/pong tile-sets + consumer scratch (~129.5KB, 1 CTA/SM) ----
#define BUF(k)   ((k) * 65536)       // fp16 S tile [128x128] (32KB) at +0
#define WOFF     32768               // fp16 W tile (32KB); becomes fp16 comm after MMA
#define VOFF     131072              // v[128] fp32
#define PSOFF    131584              // ps[256] fp32, layout [2r+half]
#define SMEM_REQ 132608

#define BAR_SYNC(id, cnt)   asm volatile("bar.sync %0, %1;"   :: "r"(id), "r"(cnt) : "memory")
#define BAR_ARRIVE(id, cnt) asm volatile("bar.arrive %0, %1;" :: "r"(id), "r"(cnt) : "memory")
#define MEMBAR_CTA()        asm volatile("membar.cta;" ::: "memory")

__device__ __forceinline__ uint32_t smem_u32(const void* p) {
    uint32_t a;
    asm("{ .reg .u64 t; cvta.to.shared.u64 t, %1; cvt.u32.u64 %0, t; }" : "=r"(a) : "l"(p));
    return a;
}
__device__ __forceinline__ void ldsm_x4(uint32_t* r, uint32_t addr) {
    asm volatile("ldmatrix.sync.aligned.m8n8.x4.shared.b16 {%0,%1,%2,%3}, [%4];"
                 : "=r"(r[0]), "=r"(r[1]), "=r"(r[2]), "=r"(r[3]) : "r"(addr));
}
__device__ __forceinline__ void ldsm_x4t(uint32_t* r, uint32_t addr) {
    asm volatile("ldmatrix.sync.aligned.m8n8.x4.trans.shared.b16 {%0,%1,%2,%3}, [%4];"
                 : "=r"(r[0]), "=r"(r[1]), "=r"(r[2]), "=r"(r[3]) : "r"(addr));
}
// fp16 in, fp16 accum (d packed f16x2: d[0]=row lr, d[1]=row lr+8)
__device__ __forceinline__ void mma16816h(uint32_t* d, const uint32_t* a, const uint32_t* b) {
    asm volatile("mma.sync.aligned.m16n8k16.row.col.f16.f16.f16.f16 "
                 "{%0,%1}, {%2,%3,%4,%5}, {%6,%7}, {%0,%1};"
                 : "+r"(d[0]), "+r"(d[1])
                 : "r"(a[0]), "r"(a[1]), "r"(a[2]), "r"(a[3]), "r"(b[0]), "r"(b[1]));
}
// fp16 tile address: pitch 256B/row (16 chunks of 16B = 8 cols), chunk ^= row&7
__device__ __forceinline__ uint32_t taddr(uint32_t base, int row, int col) {
    int chunk = (col >> 3) ^ (row & 7);
    return base + row * 256 + (chunk << 4);
}
__device__ __forceinline__ uint32_t h2u(__half2 v) { return *reinterpret_cast<uint32_t*>(&v); }

__global__ __launch_bounds__(512, 1)
void magnus_kernel(const float* __restrict__ t0, const float* __restrict__ hp,
                   const float* __restrict__ y0,
                   const float* __restrict__ A0, const float* __restrict__ Wm,
                   float* __restrict__ out, int B)
{
    extern __shared__ char sm[];
    const uint32_t sb = smem_u32(sm);

    const int tid  = threadIdx.x;
    const int wid  = tid >> 5;
    const int step = gridDim.x;
    const int b0   = blockIdx.x;

    const float h   = hp[0];
    const float h2  = 0.5f * h;
    const float c24 = h * h * h * (1.0f / 24.0f);

    if (wid < 8) {
        // ================= PRODUCER (warps 0-7, 256 threads) =================
        const int ptid = tid;
        int i = 0;
        for (int bp = b0; bp < B; bp += step, ++i) {
            const int k = i & 1;
            if (i >= 2) BAR_SYNC(3 + k, 512);        // wait: buffer k free

            const float t0b = t0[bp];
            const float t1  = t0b + (0.5f - SQ36) * h;
            const float t2  = t0b + (0.5f + SQ36) * h;

            const float4* A0g = (const float4*)(A0 + (size_t)bp * BD);
            const float4* Wg  = (const float4*)(Wm + (size_t)bp * BD);
            float4* o1 = (float4*)(out + (size_t)B * DD + (size_t)bp * BD);
            float4* o2 = (float4*)(out + (size_t)B * DD + (size_t)B * BD + (size_t)bp * BD);
            const uint32_t bufS = sb + BUF(k);
            const uint32_t bufW = bufS + WOFF;

            float4 pa[2][2], pw[2][2];
            #pragma unroll
            for (int u = 0; u < 2; ++u) {
                int idx = ptid + 256 * u;
                pa[0][u] = A0g[idx];
                pw[0][u] = Wg[idx];
            }
            #pragma unroll
            for (int gp = 0; gp < 8; ++gp) {
                int cur = gp & 1;
                if (gp < 7) {
                    #pragma unroll
                    for (int u = 0; u < 2; ++u) {
                        int idx = ptid + 256 * (2 * (gp + 1) + u);
                        pa[cur ^ 1][u] = A0g[idx];
                        pw[cur ^ 1][u] = Wg[idx];
                    }
                }
                #pragma unroll
                for (int u = 0; u < 2; ++u) {
                    int idx = ptid + 256 * (2 * gp + u);
                    int row = idx >> 5;
                    int ch  = idx & 31;          // 16B fp32 chunk (4 cols)
                    float4 a = pa[cur][u];
                    float4 w = pw[cur][u];
                    float4 x1, x2;
                    x1.x = fmaf(t1, w.x, a.x); x1.y = fmaf(t1, w.y, a.y);
                    x1.z = fmaf(t1, w.z, a.z); x1.w = fmaf(t1, w.w, a.w);
                    x2.x = fmaf(t2, w.x, a.x); x2.y = fmaf(t2, w.y, a.y);
                    x2.z = fmaf(t2, w.z, a.z); x2.w = fmaf(t2, w.w, a.w);
                    o1[idx] = x1;
                    o2[idx] = x2;
                    uint2 pS, pW;
                    pS.x = h2u(__floats2half2_rn(x1.x + x2.x, x1.y + x2.y));
                    pS.y = h2u(__floats2half2_rn(x1.z + x2.z, x1.w + x2.w));
                    pW.x = h2u(__floats2half2_rn(w.x, w.y));
                    pW.y = h2u(__floats2half2_rn(w.z, w.w));
                    uint32_t toff = (uint32_t)(row * 256 + (((ch >> 1) ^ (row & 7)) << 4) + ((ch & 1) << 3));
                    *(uint2*)(sm + BUF(k) + toff)        = pS;
                    *(uint2*)(sm + BUF(k) + WOFF + toff) = pW;
                }
            }
            MEMBAR_CTA();
            BAR_ARRIVE(1 + k, 512);                  // signal: buffer k full
        }
    } else {
        // ================= CONSUMER (warps 8-15, 256 threads) =================
        const int ctid  = tid - 256;
        const int clane = ctid & 31;
        const int cwid  = ctid >> 5;
        float* v  = (float*)(sm + VOFF);
        float* ps = (float*)(sm + PSOFF);

        const int m0 = (cwid >> 2) << 6;   // 0 or 64
        const int n0 = (cwid & 3) << 5;    // 0,32,64,96
        const int arow = clane & 15;
        const int acol = (clane >> 4) << 3;
        const int r    = ctid >> 1;
        const int half = ctid & 1;

        int i = 0;
        for (int bc = b0; bc < B; bc += step, ++i) {
            const int k = i & 1;
            BAR_SYNC(1 + k, 512);                    // wait: buffer k full
            if (ctid < DD) v[ctid] = y0[(size_t)bc * DD + ctid];

            const uint32_t aS = sb + BUF(k);
            const uint32_t aW = aS + WOFF;

            // ---- MMA: CM = S@W + (-W)@S (= [S,W]); 2x4 warp grid, 64x32/warp ----
            uint32_t acc[4][4][2];
            #pragma unroll
            for (int mh = 0; mh < 4; ++mh)
                #pragma unroll
                for (int nt = 0; nt < 4; ++nt) { acc[mh][nt][0] = 0u; acc[mh][nt][1] = 0u; }

            #pragma unroll
            for (int k0 = 0; k0 < DD; k0 += 16) {
                uint32_t fs[4][4], fw[4][4];
                #pragma unroll
                for (int mh = 0; mh < 4; ++mh) {
                    ldsm_x4(fs[mh], taddr(aS, m0 + 16 * mh + arow, k0 + acol));
                    ldsm_x4(fw[mh], taddr(aW, m0 + 16 * mh + arow, k0 + acol));
                    #pragma unroll
                    for (int qq = 0; qq < 4; ++qq) fw[mh][qq] ^= 0x80008000u;   // -W
                }
                #pragma unroll
                for (int nn = 0; nn < 2; ++nn) {
                    uint32_t bW[4], bS[4];
                    ldsm_x4t(bW, taddr(aW, k0 + arow, n0 + 16 * nn + acol));
                    ldsm_x4t(bS, taddr(aS, k0 + arow, n0 + 16 * nn + acol));
                    #pragma unroll
                    for (int mh = 0; mh < 4; ++mh) {
                        mma16816h(acc[mh][2 * nn],     fs[mh], bW);
                        mma16816h(acc[mh][2 * nn + 1], fs[mh], bW + 2);
                        mma16816h(acc[mh][2 * nn],     fw[mh], bS);
                        mma16816h(acc[mh][2 * nn + 1], fw[mh], bS + 2);
                    }
                }
            }
            BAR_SYNC(5, 256);    // all consumer ldsm of W tile done -> reusable

            // ---- store fp16 CM into W-tile region ----
            {
                const int lr = clane >> 2;
                const int lc = (clane & 3) << 1;
                #pragma unroll
                for (int mh = 0; mh < 4; ++mh)
                    #pragma unroll
                    for (int nt = 0; nt < 4; ++nt)
                        #pragma unroll
                        for (int hf = 0; hf < 2; ++hf) {
                            int row = m0 + 16 * mh + lr + 8 * hf;
                            int col = n0 + 8 * nt + lc;
                            uint32_t addr = (uint32_t)(row * 256 + (((col >> 3) ^ (row & 7)) << 4) + ((col & 7) << 1));
                            *(uint32_t*)(sm + BUF(k) + WOFF + addr) = acc[mh][nt][hf];
                        }
            }
            BAR_SYNC(5, 256);

            // ---- om[64] = h/2 * S - c24 * CM  (row r, half) ----
            float om[64];
            #pragma unroll
            for (int j = 0; j < 8; ++j) {
                uint32_t cc = (uint32_t)(r * 256 + ((8 * half + (j ^ (r & 7))) << 4));
                uint4 us = *(const uint4*)(sm + BUF(k) + cc);
                uint4 uc = *(const uint4*)(sm + BUF(k) + WOFF + cc);
                const uint32_t ss[4] = {us.x, us.y, us.z, us.w};
                const uint32_t cs[4] = {uc.x, uc.y, uc.z, uc.w};
                int jb = j * 8;
                #pragma unroll
                for (int t = 0; t < 4; ++t) {
                    float2 fs2 = __half22float2(*(const __half2*)&ss[t]);
                    float2 fc2 = __half22float2(*(const __half2*)&cs[t]);
                    om[jb + 2 * t + 0] = fmaf(h2, fs2.x, -c24 * fc2.x);
                    om[jb + 2 * t + 1] = fmaf(h2, fs2.y, -c24 * fc2.y);
                }
            }
            BAR_ARRIVE(3 + k, 512);                  // signal: buffer k free

            // ---- Taylor: y = expm(Omega) @ y0, 7 terms ----
            float yvreg = v[r];
            const float4* vv = (const float4*)(v + 64 * half);
            #pragma unroll 1
            for (int kk = 1; kk <= 7; ++kk) {
                float s0 = 0.f, s1 = 0.f, s2 = 0.f, s3 = 0.f;
                #pragma unroll
                for (int f4 = 0; f4 < 16; ++f4) {
                    float4 f = vv[f4];
                    s0 = fmaf(om[4 * f4 + 0], f.x, s0);
                    s1 = fmaf(om[4 * f4 + 1], f.y, s1);
                    s2 = fmaf(om[4 * f4 + 2], f.z, s2);
                    s3 = fmaf(om[4 * f4 + 3], f.w, s3);
                }
                ps[2 * r + half] = (s0 + s1) + (s2 + s3);
                BAR_SYNC(5, 256);
                float2 p = *(const float2*)(ps + 2 * r);
                float nv = (p.x + p.y) * (1.0f / (float)kk);
                yvreg += nv;
                if (half == 0) v[r] = nv;
                BAR_SYNC(5, 256);
            }
            if (half == 0) out[(size_t)bc * DD + r] = yvreg;
        }
    }
}

extern "C" void kernel_launch(void* const* d_in, const int* in_sizes, int n_in,
                              void* d_out, int out_size) {
    const float* t0 = (const float*)d_in[0];
    const float* h  = (const float*)d_in[1];
    const float* y0 = (const float*)d_in[2];
    const float* A0 = (const float*)d_in[3];
    const float* W  = (const float*)d_in[4];
    const int B = in_sizes[0];

    int grid = B < 152 ? B : 152;
    cudaFuncSetAttribute(magnus_kernel, cudaFuncAttributeMaxDynamicSharedMemorySize, SMEM_REQ);
    magnus_kernel<<<grid, 512, SMEM_REQ>>>(t0, h, y0, A0, W, (float*)d_out, B);
}